// round 10
// baseline (speedup 1.0000x reference)
#include <cuda_runtime.h>

#define N_NODES 100000
#define M_EDGES 800000
#define F_IN    64
#define F_E     16
#define H_DIM   64

// Scratch (no cudaMalloc allowed): h2 projections, edge-feature buckets, counts.
__device__ float g_h2[N_NODES * H_DIM];    // 25.6 MB
__device__ float g_E [N_NODES * 48];       // 19.2 MB  (3 edge types x 16 feats)
__device__ float g_C [N_NODES * 3];        //  1.2 MB  (per-type incoming-edge counts)

__device__ __forceinline__ void red_add_v4(float* p, float a, float b, float c, float d) {
    asm volatile("red.global.add.v4.f32 [%0], {%1,%2,%3,%4};"
                 :: "l"(p), "f"(a), "f"(b), "f"(c), "f"(d) : "memory");
}
__device__ __forceinline__ void red_add_f32(float* p, float a) {
    asm volatile("red.global.add.f32 [%0], %1;" :: "l"(p), "f"(a) : "memory");
}

// ---------------------------------------------------------------------------
// Kernel 0: zero the E / C scratch (graph is replayed; must re-zero each launch)
// ---------------------------------------------------------------------------
__global__ __launch_bounds__(256) void k_zero() {
    const int nE4 = N_NODES * 48 / 4;   // 1,200,000
    const int nC4 = N_NODES * 3 / 4;    //    75,000
    const float4 z = make_float4(0.f, 0.f, 0.f, 0.f);
    for (int i = blockIdx.x * 256 + threadIdx.x; i < nE4; i += gridDim.x * 256)
        reinterpret_cast<float4*>(g_E)[i] = z;
    for (int i = blockIdx.x * 256 + threadIdx.x; i < nC4; i += gridDim.x * 256)
        reinterpret_cast<float4*>(g_C)[i] = z;
}

// ---------------------------------------------------------------------------
// Kernel 1: per-node-type projections.  h1 -> out, h2 -> g_h2.
// One warp processes 8 nodes; x broadcast via shfl; both type-variants of the
// weight row are loaded once per k (shared across the 8 nodes) and selected
// per node with FSEL (alu pipe, overlaps the fma pipe).
// Dynamic smem: W1[2][64][64] + W2[2][64][64] + b1[2][64] + b2[2][64] = 66560 B
// ---------------------------------------------------------------------------
__global__ __launch_bounds__(256) void k_node(
    const float* __restrict__ x, const int* __restrict__ ntype,
    const float* __restrict__ W1, const float* __restrict__ b1,
    const float* __restrict__ W2, const float* __restrict__ b2,
    float* __restrict__ out)
{
    extern __shared__ float smem[];
    float* sW1 = smem;            // 8192 floats
    float* sW2 = smem + 8192;     // 8192 floats
    float* sb1 = smem + 16384;    // 128
    float* sb2 = smem + 16512;    // 128

    for (int i = threadIdx.x; i < 8192; i += 256) { sW1[i] = W1[i]; sW2[i] = W2[i]; }
    if (threadIdx.x < 128) { sb1[threadIdx.x] = b1[threadIdx.x]; sb2[threadIdx.x] = b2[threadIdx.x]; }
    __syncthreads();

    const int wid  = threadIdx.x >> 5;
    const int lane = threadIdx.x & 31;
    const int base = (blockIdx.x * 8 + wid) * 8;   // first of this warp's 8 nodes
    if (base >= N_NODES) return;

    float xlo[8], xhi[8];
    int   tsel[8];
    #pragma unroll
    for (int j = 0; j < 8; j++) {
        int n = base + j; if (n >= N_NODES) n = N_NODES - 1;
        xlo[j]  = x[n * 64 + lane];
        xhi[j]  = x[n * 64 + 32 + lane];
        tsel[j] = ntype[n];
    }

    float2 a1[8], a2[8];
    #pragma unroll
    for (int j = 0; j < 8; j++) {
        a1[j] = *reinterpret_cast<const float2*>(&sb1[tsel[j] * 64 + 2 * lane]);
        a2[j] = *reinterpret_cast<const float2*>(&sb2[tsel[j] * 64 + 2 * lane]);
    }

    const float2* pW1 = reinterpret_cast<const float2*>(sW1);  // [type][k][32 float2]
    const float2* pW2 = reinterpret_cast<const float2*>(sW2);

    #pragma unroll 4
    for (int k = 0; k < 32; k++) {
        float2 w1a = pW1[k * 32 + lane];
        float2 w1b = pW1[2048 + k * 32 + lane];
        float2 w2a = pW2[k * 32 + lane];
        float2 w2b = pW2[2048 + k * 32 + lane];
        #pragma unroll
        for (int j = 0; j < 8; j++) {
            float  xk = __shfl_sync(0xffffffffu, xlo[j], k);
            float2 w1 = tsel[j] ? w1b : w1a;
            float2 w2 = tsel[j] ? w2b : w2a;
            a1[j].x += xk * w1.x; a1[j].y += xk * w1.y;
            a2[j].x += xk * w2.x; a2[j].y += xk * w2.y;
        }
    }
    #pragma unroll 4
    for (int k = 32; k < 64; k++) {
        float2 w1a = pW1[k * 32 + lane];
        float2 w1b = pW1[2048 + k * 32 + lane];
        float2 w2a = pW2[k * 32 + lane];
        float2 w2b = pW2[2048 + k * 32 + lane];
        #pragma unroll
        for (int j = 0; j < 8; j++) {
            float  xk = __shfl_sync(0xffffffffu, xhi[j], k - 32);
            float2 w1 = tsel[j] ? w1b : w1a;
            float2 w2 = tsel[j] ? w2b : w2a;
            a1[j].x += xk * w1.x; a1[j].y += xk * w1.y;
            a2[j].x += xk * w2.x; a2[j].y += xk * w2.y;
        }
    }

    #pragma unroll
    for (int j = 0; j < 8; j++) {
        int n = base + j;
        if (n < N_NODES) {
            *reinterpret_cast<float2*>(&out [n * 64 + 2 * lane]) = a1[j];
            *reinterpret_cast<float2*>(&g_h2[n * 64 + 2 * lane]) = a2[j];
        }
    }
}

// ---------------------------------------------------------------------------
// Kernel 2: edge scatter. 16 threads per edge.
//   out[dst] += h2[src]            (16 x red.v4, one per lane-group member)
//   E[dst][etype] += edge_feat     ( 4 x red.v4, lanes g<4)
//   C[dst][etype] += 1             ( 1 x red,    lane g==0)
// Index loads are issued first so the h2 load + all reds batch in the L1tex
// queue (reds are no-return; no dependence stalls after issue).
// ---------------------------------------------------------------------------
__global__ __launch_bounds__(256) void k_edge(
    const float* __restrict__ feat,
    const int*  __restrict__ esrc, const int* __restrict__ edst,
    const int*  __restrict__ etype,
    float* __restrict__ out)
{
    int tid = blockIdx.x * 256 + threadIdx.x;
    int e = tid >> 4;
    int g = tid & 15;
    if (e >= M_EDGES) return;

    const int src = __ldg(&esrc[e]);
    const int dst = __ldg(&edst[e]);
    const int t   = __ldg(&etype[e]);

    const float4 hv = *reinterpret_cast<const float4*>(&g_h2[(size_t)src * 64 + g * 4]);

    if (g < 4) {
        const float4 f = *reinterpret_cast<const float4*>(&feat[(size_t)e * 16 + g * 4]);
        red_add_v4(&g_E[(size_t)dst * 48 + t * 16 + g * 4], f.x, f.y, f.z, f.w);
        if (g == 0) red_add_f32(&g_C[dst * 3 + t], 1.0f);
    }
    red_add_v4(&out[(size_t)dst * 64 + g * 4], hv.x, hv.y, hv.z, hv.w);
}

// ---------------------------------------------------------------------------
// Kernel 3: per-node epilogue: out[i] += sum_t E[i][t]*W5[t] + C[i][t]*b5[t]
// Same warp-per-8-nodes shuffle-broadcast structure as k_node.
// ---------------------------------------------------------------------------
__global__ __launch_bounds__(256) void k_post(
    const float* __restrict__ W5, const float* __restrict__ b5,
    float* __restrict__ out)
{
    __shared__ float sW5[3 * 16 * 64];   // 12 KB, [t*16+k][64]
    __shared__ float sb5[3 * 64];
    for (int i = threadIdx.x; i < 3072; i += 256) sW5[i] = W5[i];
    if (threadIdx.x < 192) sb5[threadIdx.x] = b5[threadIdx.x];
    __syncthreads();

    const int wid  = threadIdx.x >> 5;
    const int lane = threadIdx.x & 31;
    const int base = (blockIdx.x * 8 + wid) * 8;
    if (base >= N_NODES) return;

    float e0[8], e1[8];
    float2 acc[8];
    #pragma unroll
    for (int j = 0; j < 8; j++) {
        int n = base + j; if (n >= N_NODES) n = N_NODES - 1;
        e0[j] = g_E[n * 48 + lane];
        e1[j] = (lane < 16) ? g_E[n * 48 + 32 + lane] : 0.f;
        acc[j] = make_float2(0.f, 0.f);
    }

    const float2* pW5 = reinterpret_cast<const float2*>(sW5);   // [48][32 float2]
    #pragma unroll 4
    for (int k = 0; k < 32; k++) {
        float2 w = pW5[k * 32 + lane];
        #pragma unroll
        for (int j = 0; j < 8; j++) {
            float ek = __shfl_sync(0xffffffffu, e0[j], k);
            acc[j].x += ek * w.x; acc[j].y += ek * w.y;
        }
    }
    #pragma unroll 4
    for (int k = 32; k < 48; k++) {
        float2 w = pW5[k * 32 + lane];
        #pragma unroll
        for (int j = 0; j < 8; j++) {
            float ek = __shfl_sync(0xffffffffu, e1[j], k - 32);
            acc[j].x += ek * w.x; acc[j].y += ek * w.y;
        }
    }

    const float2* pb5 = reinterpret_cast<const float2*>(sb5);   // [t][32 float2]
    float2 bb0 = pb5[lane], bb1 = pb5[32 + lane], bb2 = pb5[64 + lane];

    #pragma unroll
    for (int j = 0; j < 8; j++) {
        int n = base + j;
        if (n >= N_NODES) break;
        float c0 = g_C[n * 3 + 0], c1 = g_C[n * 3 + 1], c2 = g_C[n * 3 + 2];
        acc[j].x += c0 * bb0.x + c1 * bb1.x + c2 * bb2.x;
        acc[j].y += c0 * bb0.y + c1 * bb1.y + c2 * bb2.y;
        float2 o = *reinterpret_cast<float2*>(&out[n * 64 + 2 * lane]);
        o.x += acc[j].x; o.y += acc[j].y;
        *reinterpret_cast<float2*>(&out[n * 64 + 2 * lane]) = o;
    }
}

// ---------------------------------------------------------------------------
// Launch. Inputs identified by element count. Robust to both metadata orders
// (signature order and setup-dict order): in each, the first two 8192-float
// arrays are W1,W2; the first two 128-float arrays are b1,b2; the three
// 800000-int arrays are esrc,edst,etype in order. Dead inputs (W3,W4,b3,b4)
// are skipped by the counters.
// ---------------------------------------------------------------------------
extern "C" void kernel_launch(void* const* d_in, const int* in_sizes, int n_in,
                              void* d_out, int out_size)
{
    const float *x = nullptr, *feat = nullptr;
    const float *W1 = nullptr, *b1 = nullptr, *W2 = nullptr, *b2 = nullptr;
    const float *W5 = nullptr, *b5 = nullptr;
    const int *ntype = nullptr, *esrc = nullptr, *edst = nullptr, *etype = nullptr;
    int c800k = 0, c8192 = 0, c128 = 0;

    for (int i = 0; i < n_in; i++) {
        int s = in_sizes[i]; const void* p = d_in[i];
        if      (s == N_NODES * F_IN) x    = (const float*)p;
        else if (s == M_EDGES * F_E)  feat = (const float*)p;
        else if (s == N_NODES)        ntype = (const int*)p;
        else if (s == M_EDGES) {
            if      (c800k == 0) esrc  = (const int*)p;
            else if (c800k == 1) edst  = (const int*)p;
            else if (c800k == 2) etype = (const int*)p;
            c800k++;
        }
        else if (s == 8192) { if (c8192 == 0) W1 = (const float*)p; else if (c8192 == 1) W2 = (const float*)p; c8192++; }
        else if (s == 128)  { if (c128  == 0) b1 = (const float*)p; else if (c128  == 1) b2 = (const float*)p; c128++; }
        else if (s == 3072) W5 = (const float*)p;
        else if (s == 192)  b5 = (const float*)p;
    }

    float* out = (float*)d_out;

    // 0) zero scratch buckets (~21 MB of stores)
    k_zero<<<2048, 256>>>();
    // 1) node projections (h1 -> out, h2 -> g_h2); 66560 B dynamic smem
    cudaFuncSetAttribute(k_node, cudaFuncAttributeMaxDynamicSharedMemorySize, 66560);
    int nblocks_node = (N_NODES + 63) / 64;
    k_node<<<nblocks_node, 256, 66560>>>(x, ntype, W1, b1, W2, b2, out);
    // 2) edge scatter (atomics)
    k_edge<<<(M_EDGES * 16) / 256, 256>>>(feat, esrc, edst, etype, out);
    // 3) node epilogue (E*W5 + counts*b5)
    k_post<<<nblocks_node, 256>>>(W5, b5, out);
}

// round 13
// speedup vs baseline: 1.0331x; 1.0331x over previous
#include <cuda_runtime.h>

#define N_NODES 100000
#define M_EDGES 800000
#define F_IN    64
#define F_E     16
#define H_DIM   64

// Scratch (no cudaMalloc allowed): h2 projections, edge-feature buckets, counts.
__device__ float g_h2[N_NODES * H_DIM];    // 25.6 MB
__device__ float g_E [N_NODES * 48];       // 19.2 MB  (3 edge types x 16 feats)
__device__ float g_C [N_NODES * 3];        //  1.2 MB  (per-type incoming-edge counts)

__device__ __forceinline__ void red_add_v4(float* p, float a, float b, float c, float d) {
    asm volatile("red.global.add.v4.f32 [%0], {%1,%2,%3,%4};"
                 :: "l"(p), "f"(a), "f"(b), "f"(c), "f"(d) : "memory");
}
__device__ __forceinline__ void red_add_f32(float* p, float a) {
    asm volatile("red.global.add.f32 [%0], %1;" :: "l"(p), "f"(a) : "memory");
}

// ---------------------------------------------------------------------------
// Kernel 1: zeroing prologue + per-node-type projections.
// Zeroing of g_E/g_C folded in (was k_zero): completes before k_edge by
// kernel-boundary ordering; overlaps with weight staging here.
// h1 -> out, h2 -> g_h2. One warp processes 8 nodes; x broadcast via shfl;
// both type-variants of the weight row loaded once per k, FSEL per node.
// Dynamic smem: W1[2][64][64] + W2[2][64][64] + b1[2][64] + b2[2][64] = 66560 B
// ---------------------------------------------------------------------------
__global__ __launch_bounds__(256) void k_node(
    const float* __restrict__ x, const int* __restrict__ ntype,
    const float* __restrict__ W1, const float* __restrict__ b1,
    const float* __restrict__ W2, const float* __restrict__ b2,
    float* __restrict__ out)
{
    // --- integrated scratch zeroing (grid-stride over whole grid) ---
    {
        const int nE4 = N_NODES * 48 / 4;   // 1,200,000
        const int nC4 = N_NODES * 3 / 4;    //    75,000
        const float4 z = make_float4(0.f, 0.f, 0.f, 0.f);
        for (int i = blockIdx.x * 256 + threadIdx.x; i < nE4; i += gridDim.x * 256)
            reinterpret_cast<float4*>(g_E)[i] = z;
        for (int i = blockIdx.x * 256 + threadIdx.x; i < nC4; i += gridDim.x * 256)
            reinterpret_cast<float4*>(g_C)[i] = z;
    }

    extern __shared__ float smem[];
    float* sW1 = smem;            // 8192 floats
    float* sW2 = smem + 8192;     // 8192 floats
    float* sb1 = smem + 16384;    // 128
    float* sb2 = smem + 16512;    // 128

    for (int i = threadIdx.x; i < 8192; i += 256) { sW1[i] = W1[i]; sW2[i] = W2[i]; }
    if (threadIdx.x < 128) { sb1[threadIdx.x] = b1[threadIdx.x]; sb2[threadIdx.x] = b2[threadIdx.x]; }
    __syncthreads();

    const int wid  = threadIdx.x >> 5;
    const int lane = threadIdx.x & 31;
    const int base = (blockIdx.x * 8 + wid) * 8;   // first of this warp's 8 nodes
    if (base >= N_NODES) return;

    float xlo[8], xhi[8];
    int   tsel[8];
    #pragma unroll
    for (int j = 0; j < 8; j++) {
        int n = base + j; if (n >= N_NODES) n = N_NODES - 1;
        xlo[j]  = x[n * 64 + lane];
        xhi[j]  = x[n * 64 + 32 + lane];
        tsel[j] = ntype[n];
    }

    float2 a1[8], a2[8];
    #pragma unroll
    for (int j = 0; j < 8; j++) {
        a1[j] = *reinterpret_cast<const float2*>(&sb1[tsel[j] * 64 + 2 * lane]);
        a2[j] = *reinterpret_cast<const float2*>(&sb2[tsel[j] * 64 + 2 * lane]);
    }

    const float2* pW1 = reinterpret_cast<const float2*>(sW1);  // [type][k][32 float2]
    const float2* pW2 = reinterpret_cast<const float2*>(sW2);

    #pragma unroll 4
    for (int k = 0; k < 32; k++) {
        float2 w1a = pW1[k * 32 + lane];
        float2 w1b = pW1[2048 + k * 32 + lane];
        float2 w2a = pW2[k * 32 + lane];
        float2 w2b = pW2[2048 + k * 32 + lane];
        #pragma unroll
        for (int j = 0; j < 8; j++) {
            float  xk = __shfl_sync(0xffffffffu, xlo[j], k);
            float2 w1 = tsel[j] ? w1b : w1a;
            float2 w2 = tsel[j] ? w2b : w2a;
            a1[j].x += xk * w1.x; a1[j].y += xk * w1.y;
            a2[j].x += xk * w2.x; a2[j].y += xk * w2.y;
        }
    }
    #pragma unroll 4
    for (int k = 32; k < 64; k++) {
        float2 w1a = pW1[k * 32 + lane];
        float2 w1b = pW1[2048 + k * 32 + lane];
        float2 w2a = pW2[k * 32 + lane];
        float2 w2b = pW2[2048 + k * 32 + lane];
        #pragma unroll
        for (int j = 0; j < 8; j++) {
            float  xk = __shfl_sync(0xffffffffu, xhi[j], k - 32);
            float2 w1 = tsel[j] ? w1b : w1a;
            float2 w2 = tsel[j] ? w2b : w2a;
            a1[j].x += xk * w1.x; a1[j].y += xk * w1.y;
            a2[j].x += xk * w2.x; a2[j].y += xk * w2.y;
        }
    }

    #pragma unroll
    for (int j = 0; j < 8; j++) {
        int n = base + j;
        if (n < N_NODES) {
            *reinterpret_cast<float2*>(&out [n * 64 + 2 * lane]) = a1[j];
            *reinterpret_cast<float2*>(&g_h2[n * 64 + 2 * lane]) = a2[j];
        }
    }
}

// ---------------------------------------------------------------------------
// Kernel 2: edge scatter. 16 threads per edge.
//   out[dst] += h2[src]            (16 x red.v4, one per lane-group member)
//   E[dst][etype] += edge_feat     ( 4 x red.v4, lanes g<4)
//   C[dst][etype] += 1             ( 1 x red,    lane g==0)
// ---------------------------------------------------------------------------
__global__ __launch_bounds__(256) void k_edge(
    const float* __restrict__ feat,
    const int*  __restrict__ esrc, const int* __restrict__ edst,
    const int*  __restrict__ etype,
    float* __restrict__ out)
{
    int tid = blockIdx.x * 256 + threadIdx.x;
    int e = tid >> 4;
    int g = tid & 15;
    if (e >= M_EDGES) return;

    const int src = __ldg(&esrc[e]);
    const int dst = __ldg(&edst[e]);
    const int t   = __ldg(&etype[e]);

    const float4 hv = *reinterpret_cast<const float4*>(&g_h2[(size_t)src * 64 + g * 4]);

    if (g < 4) {
        const float4 f = *reinterpret_cast<const float4*>(&feat[(size_t)e * 16 + g * 4]);
        red_add_v4(&g_E[(size_t)dst * 48 + t * 16 + g * 4], f.x, f.y, f.z, f.w);
        if (g == 0) red_add_f32(&g_C[dst * 3 + t], 1.0f);
    }
    red_add_v4(&out[(size_t)dst * 64 + g * 4], hv.x, hv.y, hv.z, hv.w);
}

// ---------------------------------------------------------------------------
// Kernel 3: per-node epilogue: out[i] += sum_t E[i][t]*W5[t] + C[i][t]*b5[t]
// R10 ncu showed L1/MIO-bound (58.6% L1, 21.7% fma): 16 nodes per warp,
// half-warp handles 8 nodes, lane covers 4 h-columns (float4), E preloaded
// to 24 regs/lane, broadcast via shfl width=16. Per k-iter per warp:
// 1 LDS.128 + 8 SHFL + 32 FFMA for 1024 MACs — MIO ops/node halved vs R10.
// ---------------------------------------------------------------------------
__global__ __launch_bounds__(256) void k_post(
    const float* __restrict__ W5, const float* __restrict__ b5,
    float* __restrict__ out)
{
    __shared__ float sW5[3 * 16 * 64];   // 12 KB, [k48][64] with k48 = t*16+f
    __shared__ float sb5[3 * 64];
    for (int i = threadIdx.x; i < 3072; i += 256) sW5[i] = W5[i];
    if (threadIdx.x < 192) sb5[threadIdx.x] = b5[threadIdx.x];
    __syncthreads();

    const int wid  = threadIdx.x >> 5;
    const int lane = threadIdx.x & 31;
    const int half = lane >> 4;          // 0 or 1
    const int hl   = lane & 15;          // lane within half
    // warp handles 16 nodes; this half handles 8 of them
    const int base = (blockIdx.x * 8 + wid) * 16 + half * 8;

    // Preload E: lane hl holds E[node j][c*16 + hl], j=0..7, c=0..2
    float e_reg[24];
    #pragma unroll
    for (int j = 0; j < 8; j++) {
        int n = base + j; if (n >= N_NODES) n = N_NODES - 1;
        #pragma unroll
        for (int c = 0; c < 3; c++)
            e_reg[j * 3 + c] = g_E[(size_t)n * 48 + c * 16 + hl];
    }

    float4 acc[8];
    #pragma unroll
    for (int j = 0; j < 8; j++) acc[j] = make_float4(0.f, 0.f, 0.f, 0.f);

    const float4* pW = reinterpret_cast<const float4*>(sW5);   // [48][16 float4]
    #pragma unroll
    for (int c = 0; c < 3; c++) {
        #pragma unroll 4
        for (int idx = 0; idx < 16; idx++) {
            float4 w = pW[(c * 16 + idx) * 16 + hl];
            #pragma unroll
            for (int j = 0; j < 8; j++) {
                float e = __shfl_sync(0xffffffffu, e_reg[j * 3 + c], idx, 16);
                acc[j].x += e * w.x; acc[j].y += e * w.y;
                acc[j].z += e * w.z; acc[j].w += e * w.w;
            }
        }
    }

    const float4* pb = reinterpret_cast<const float4*>(sb5);   // [3][16 float4]
    const float4 bb0 = pb[hl], bb1 = pb[16 + hl], bb2 = pb[32 + hl];

    #pragma unroll
    for (int j = 0; j < 8; j++) {
        int n = base + j;
        if (n >= N_NODES) break;
        float c0 = g_C[n * 3 + 0], c1 = g_C[n * 3 + 1], c2 = g_C[n * 3 + 2];
        acc[j].x += c0 * bb0.x + c1 * bb1.x + c2 * bb2.x;
        acc[j].y += c0 * bb0.y + c1 * bb1.y + c2 * bb2.y;
        acc[j].z += c0 * bb0.z + c1 * bb1.z + c2 * bb2.z;
        acc[j].w += c0 * bb0.w + c1 * bb1.w + c2 * bb2.w;
        float4* po = reinterpret_cast<float4*>(&out[(size_t)n * 64 + hl * 4]);
        float4 o = *po;
        o.x += acc[j].x; o.y += acc[j].y; o.z += acc[j].z; o.w += acc[j].w;
        *po = o;
    }
}

// ---------------------------------------------------------------------------
// Launch. Inputs identified by element count (robust to both metadata orders;
// dead inputs W3/W4/b3/b4 harmlessly consumed by the counters).
// ---------------------------------------------------------------------------
extern "C" void kernel_launch(void* const* d_in, const int* in_sizes, int n_in,
                              void* d_out, int out_size)
{
    const float *x = nullptr, *feat = nullptr;
    const float *W1 = nullptr, *b1 = nullptr, *W2 = nullptr, *b2 = nullptr;
    const float *W5 = nullptr, *b5 = nullptr;
    const int *ntype = nullptr, *esrc = nullptr, *edst = nullptr, *etype = nullptr;
    int c800k = 0, c8192 = 0, c128 = 0;

    for (int i = 0; i < n_in; i++) {
        int s = in_sizes[i]; const void* p = d_in[i];
        if      (s == N_NODES * F_IN) x    = (const float*)p;
        else if (s == M_EDGES * F_E)  feat = (const float*)p;
        else if (s == N_NODES)        ntype = (const int*)p;
        else if (s == M_EDGES) {
            if      (c800k == 0) esrc  = (const int*)p;
            else if (c800k == 1) edst  = (const int*)p;
            else if (c800k == 2) etype = (const int*)p;
            c800k++;
        }
        else if (s == 8192) { if (c8192 == 0) W1 = (const float*)p; else if (c8192 == 1) W2 = (const float*)p; c8192++; }
        else if (s == 128)  { if (c128  == 0) b1 = (const float*)p; else if (c128  == 1) b2 = (const float*)p; c128++; }
        else if (s == 3072) W5 = (const float*)p;
        else if (s == 192)  b5 = (const float*)p;
    }

    float* out = (float*)d_out;

    // 1) zero scratch + node projections (h1 -> out, h2 -> g_h2)
    cudaFuncSetAttribute(k_node, cudaFuncAttributeMaxDynamicSharedMemorySize, 66560);
    int nblocks_node = (N_NODES + 63) / 64;          // 1563
    k_node<<<nblocks_node, 256, 66560>>>(x, ntype, W1, b1, W2, b2, out);
    // 2) edge scatter (atomics)
    k_edge<<<(M_EDGES * 16) / 256, 256>>>(feat, esrc, edst, etype, out);
    // 3) node epilogue (E*W5 + counts*b5), 128 nodes per block
    int nblocks_post = (N_NODES + 127) / 128;        // 782
    k_post<<<nblocks_post, 256>>>(W5, b5, out);
}